// round 11
// baseline (speedup 1.0000x reference)
#include <cuda_runtime.h>
#include <cstdint>
#include <cstdio>

#define Bsz   4
#define Sln   8192
#define DIM   512
#define NH    8
#define NKV   4
#define HD    64
#define NTOK  (Bsz*Sln)          // 32768
#define KVDIM (NKV*HD)           // 256
#define GK    512
#define BK    32
#define QKVN  1024               // Q(512) | [K_h V_h] x 4 (128 each)

// ---------------- scratch (device globals; no allocation allowed) ----------
__device__ float g_xn [(size_t)NTOK * DIM];    // x after rmsnorm (tf32-valued); later Y
__device__ float g_qkv[(size_t)NTOK * QKVN];   // only Q region [0,512) is written/used
__device__ float g_w  [QKVN * DIM];            // tf32-rounded [wq | interleaved wk/wv]
__device__ float g_wo [DIM * DIM];             // tf32-rounded wo
__device__ float g_cos[Sln * 32];
__device__ float g_sin[Sln * 32];
__device__ float g_pkv[64 * 16 * 64];          // [chunk][b*4+hk][64]
__device__ float g_pks[64 * 16 * 64];
__device__ float g_kv [16 * 64];
__device__ float g_ks [16 * 64];

// ======================= helpers =======================
__device__ __forceinline__ float f2tf(float f) {
    uint32_t o;
    asm("cvt.rn.tf32.f32 %0, %1;" : "=r"(o) : "f"(f));
    return __uint_as_float(o);
}
__device__ __forceinline__ void mma_tf32(float* d, const uint32_t* a, const uint32_t* b) {
    asm volatile(
        "mma.sync.aligned.m16n8k8.row.col.f32.tf32.tf32.f32 "
        "{%0,%1,%2,%3}, {%4,%5,%6,%7}, {%8,%9}, {%0,%1,%2,%3};"
        : "+f"(d[0]), "+f"(d[1]), "+f"(d[2]), "+f"(d[3])
        : "r"(a[0]), "r"(a[1]), "r"(a[2]), "r"(a[3]), "r"(b[0]), "r"(b[1]));
}
__device__ __forceinline__ void cp_async16(uint32_t dst, const void* src) {
    asm volatile("cp.async.cg.shared.global [%0], [%1], 16;" :: "r"(dst), "l"(src));
}
__device__ __forceinline__ void cp_commit() {
    asm volatile("cp.async.commit_group;" ::: "memory");
}
__device__ __forceinline__ void cp_wait1() {
    asm volatile("cp.async.wait_group 1;" ::: "memory");
}
__device__ __forceinline__ float elu1(float v) {
    return v > 0.f ? v + 1.f : expf(v);
}

// round a buffer to tf32 values
__global__ __launch_bounds__(256) void round_tf32_kernel(float* __restrict__ dst,
                                                         const float* __restrict__ src,
                                                         int n4) {
    int i = blockIdx.x * blockDim.x + threadIdx.x;
    if (i >= n4) return;
    float4 v = ((const float4*)src)[i];
    v.x = f2tf(v.x); v.y = f2tf(v.y); v.z = f2tf(v.z); v.w = f2tf(v.w);
    ((float4*)dst)[i] = v;
}

// round + pack wk/wv rows into interleaved layout:
// src row r (= hk*64 + d) -> g_w row 512 + hk*128 + (is_v?64:0) + d
__global__ __launch_bounds__(128) void round_pack_kv(const float* __restrict__ src,
                                                     int is_v) {
    int r  = blockIdx.x;            // 0..255
    int c4 = threadIdx.x;           // 0..127 float4 over 512 cols
    float4 v = ((const float4*)(src + (size_t)r * DIM))[c4];
    v.x = f2tf(v.x); v.y = f2tf(v.y); v.z = f2tf(v.z); v.w = f2tf(v.w);
    int dstrow = 512 + (r >> 6) * 128 + (is_v ? 64 : 0) + (r & 63);
    ((float4*)(g_w + (size_t)dstrow * DIM))[c4] = v;
}

// ======================= tf32 mma.sync GEMM, cp.async 3-stage =======================
// C[M,N] = A[M,512] * B[N,512]^T. Block 128x128, BK=32, 128 thr = 4 warps (2m x 2n),
// warp tile 64x64. Inputs MUST be tf32-valued (pre-rounded).
// mode==1 (QKV): bn<512 -> RoPE+phi epilogue store (Q); bn>=512 -> fused KV/Ksum
//                partial reduction (NO gmem store of K/V).
// mode==0: plain store.
#define NSTAGE   3
#define STAGE_FL 8192
#define G_SMEM_BYTES (NSTAGE * STAGE_FL * 4)   // 98304

__global__ void __launch_bounds__(128, 2) gemm_tf32mma(const float* __restrict__ A,
                                                       const float* __restrict__ B,
                                                       float* __restrict__ C, int N,
                                                       int mode) {
    extern __shared__ float sm[];
    const uint32_t sbase = (uint32_t)__cvta_generic_to_shared(sm);
    const int tid  = threadIdx.x;
    const int wid  = tid >> 5, lane = tid & 31;
    const int wm   = wid & 1,  wn   = wid >> 1;
    const int bm   = blockIdx.y * 128;
    const int bn   = blockIdx.x * 128;

    const int rb  = tid >> 3;                      // base row 0..15 (+16i)
    const int gb  = tid & 7;                       // k4-group
    const int swb = ((gb ^ (rb & 7)) << 2);        // swizzled float offset in row

#define ISSUE(s, buf)                                                             \
    {                                                                             \
        const float* As = A + (size_t)(bm + rb) * GK + (s) * BK + gb * 4;         \
        const float* Bs = B + (size_t)(bn + rb) * GK + (s) * BK + gb * 4;         \
        uint32_t da = sbase + (uint32_t)((buf) * STAGE_FL + rb * 32 + swb) * 4;   \
        uint32_t db = da + 4096 * 4;                                              \
        _Pragma("unroll")                                                         \
        for (int i = 0; i < 8; i++) {                                             \
            cp_async16(da + i * (512 * 4), As + (size_t)i * 16 * GK);             \
            cp_async16(db + i * (512 * 4), Bs + (size_t)i * 16 * GK);             \
        }                                                                         \
    }

    float acc[4][8][4];
    #pragma unroll
    for (int mt = 0; mt < 4; mt++)
        #pragma unroll
        for (int nt = 0; nt < 8; nt++)
            #pragma unroll
            for (int r = 0; r < 4; r++) acc[mt][nt][r] = 0.f;

    ISSUE(0, 0); cp_commit();
    ISSUE(1, 1); cp_commit();

    const int lg = lane >> 2, lc = lane & 3;
    int buf = 0;
    #pragma unroll 1
    for (int s = 0; s < 16; s++) {
        cp_wait1();
        __syncthreads();
        const float* sA = sm + buf * STAGE_FL;
        const float* sB = sA + 4096;
        #pragma unroll
        for (int ks = 0; ks < 4; ks++) {
            const int g0 = 2 * ks, g1 = 2 * ks + 1;
            uint32_t af[4][4], bf[8][2];
            #pragma unroll
            for (int mt = 0; mt < 4; mt++) {
                int r = wm * 64 + mt * 16 + lg;
                int s0 = ((g0 ^ (r & 7)) << 2) + lc;
                int s1 = ((g1 ^ (r & 7)) << 2) + lc;
                af[mt][0] = __float_as_uint(sA[r * 32 + s0]);
                af[mt][1] = __float_as_uint(sA[(r + 8) * 32 + s0]);
                af[mt][2] = __float_as_uint(sA[r * 32 + s1]);
                af[mt][3] = __float_as_uint(sA[(r + 8) * 32 + s1]);
            }
            #pragma unroll
            for (int nt = 0; nt < 8; nt++) {
                int n = wn * 64 + nt * 8 + lg;
                bf[nt][0] = __float_as_uint(sB[n * 32 + ((g0 ^ (n & 7)) << 2) + lc]);
                bf[nt][1] = __float_as_uint(sB[n * 32 + ((g1 ^ (n & 7)) << 2) + lc]);
            }
            #pragma unroll
            for (int mt = 0; mt < 4; mt++)
                #pragma unroll
                for (int nt = 0; nt < 8; nt++)
                    mma_tf32(acc[mt][nt], af[mt], bf[nt]);
        }
        if (s + 2 < 16) {
            int nb = buf + 2; if (nb >= 3) nb -= 3;
            ISSUE(s + 2, nb);
        }
        cp_commit();
        if (++buf == 3) buf = 0;
    }

    // ---------------- epilogues ----------------
    if (mode == 1 && bn >= 512) {
        // KV tile: cols [0,64) of tile = K_hk, cols [64,128) = V_hk. Fused
        // rope+phi(K) and partial KV/Ksum reduction over this CTA's 128 tokens.
        const int hk = (bn - 512) >> 7;
        __syncthreads();                 // mainloop smem reads done in all warps
        float* sK = sm;                  // [128][66] padded
        float* sV = sm + 8448;           // [128][66]
        #pragma unroll
        for (int mt = 0; mt < 4; mt++) {
            int r0 = wm * 64 + mt * 16 + lg;
            int r1 = r0 + 8;
            #pragma unroll
            for (int nt = 0; nt < 8; nt++) {
                float2 lo = {acc[mt][nt][0], acc[mt][nt][1]};
                float2 hi = {acc[mt][nt][2], acc[mt][nt][3]};
                if (wn == 0) {           // K half: rope + phi
                    int j  = nt * 4 + lc;
                    int sq0 = (bm + r0) & (Sln - 1);
                    int sq1 = (bm + r1) & (Sln - 1);
                    float c0 = g_cos[sq0 * 32 + j], n0 = g_sin[sq0 * 32 + j];
                    float c1 = g_cos[sq1 * 32 + j], n1 = g_sin[sq1 * 32 + j];
                    lo = make_float2(elu1(lo.x * c0 - lo.y * n0),
                                     elu1(lo.x * n0 + lo.y * c0));
                    hi = make_float2(elu1(hi.x * c1 - hi.y * n1),
                                     elu1(hi.x * n1 + hi.y * c1));
                }
                float* dstb = (wn == 0) ? sK : sV;
                *(float2*)(dstb + r0 * 66 + nt * 8 + lc * 2) = lo;
                *(float2*)(dstb + r1 * 66 + nt * 8 + lc * 2) = hi;
            }
        }
        __syncthreads();
        {
            int j2 = tid & 63, sl = tid >> 6;      // dim, token-half
            float akv = 0.f, ak = 0.f;
            #pragma unroll 4
            for (int t = 0; t < 64; t++) {
                int tok = sl * 64 + t;
                float kk = sK[tok * 66 + j2];
                akv += kk * sV[tok * 66 + j2];
                ak  += kk;
            }
            float* part = sm + 16896;              // 256 floats
            part[tid]       = akv;
            part[128 + tid] = ak;
            __syncthreads();
            if (sl == 0) {
                akv += part[64 + j2];
                ak  += part[128 + 64 + j2];
                int b = bm >> 13, chunk = (bm & (Sln - 1)) >> 7;
                int idx = (chunk * 16 + b * 4 + hk) * 64 + j2;
                g_pkv[idx] = akv;
                g_pks[idx] = ak;
            }
        }
    } else if (mode == 1) {
        // Q region: RoPE + phi on (even,odd) column pairs, store
        #pragma unroll
        for (int mt = 0; mt < 4; mt++) {
            int t0 = bm + wm * 64 + mt * 16 + lg;
            int t1 = t0 + 8;
            int s0 = t0 & (Sln - 1), s1 = t1 & (Sln - 1);
            float* cr0 = C + (size_t)t0 * N + bn + wn * 64;
            float* cr1 = C + (size_t)t1 * N + bn + wn * 64;
            #pragma unroll
            for (int nt = 0; nt < 8; nt++) {
                int col = bn + wn * 64 + nt * 8 + lc * 2;
                int j = (col & 63) >> 1;
                float c0 = g_cos[s0 * 32 + j], n0 = g_sin[s0 * 32 + j];
                float c1 = g_cos[s1 * 32 + j], n1 = g_sin[s1 * 32 + j];
                float xr = acc[mt][nt][0], xi = acc[mt][nt][1];
                float yr = acc[mt][nt][2], yi = acc[mt][nt][3];
                float2 o0 = { elu1(xr * c0 - xi * n0), elu1(xr * n0 + xi * c0) };
                float2 o1 = { elu1(yr * c1 - yi * n1), elu1(yr * n1 + yi * c1) };
                *(float2*)(cr0 + nt * 8 + lc * 2) = o0;
                *(float2*)(cr1 + nt * 8 + lc * 2) = o1;
            }
        }
    } else {
        #pragma unroll
        for (int mt = 0; mt < 4; mt++) {
            float* cr0 = C + (size_t)(bm + wm * 64 + mt * 16 + lg) * N + bn + wn * 64;
            float* cr1 = cr0 + (size_t)8 * N;
            #pragma unroll
            for (int nt = 0; nt < 8; nt++) {
                float2 o0 = {acc[mt][nt][0], acc[mt][nt][1]};
                float2 o1 = {acc[mt][nt][2], acc[mt][nt][3]};
                *(float2*)(cr0 + nt * 8 + lc * 2) = o0;
                *(float2*)(cr1 + nt * 8 + lc * 2) = o1;
            }
        }
    }
#undef ISSUE
}

// ---------------- RMSNorm: one block per token; output tf32-valued -------------
__global__ __launch_bounds__(128) void rmsnorm_kernel(const float* __restrict__ x,
                                                      const float* __restrict__ w) {
    int t = blockIdx.x;
    const float4* xr = (const float4*)(x + (size_t)t * DIM);
    float4 v = xr[threadIdx.x];
    float ss = v.x*v.x + v.y*v.y + v.z*v.z + v.w*v.w;
    #pragma unroll
    for (int o = 16; o; o >>= 1) ss += __shfl_xor_sync(0xffffffffu, ss, o);
    __shared__ float sred[4];
    if ((threadIdx.x & 31) == 0) sred[threadIdx.x >> 5] = ss;
    __syncthreads();
    float tot = sred[0] + sred[1] + sred[2] + sred[3];
    float rs = rsqrtf(tot * (1.0f / DIM) + 1e-6f);
    const float4* wr = (const float4*)w;
    float4 wv = wr[threadIdx.x];
    float4 o;
    o.x = f2tf(v.x * rs * wv.x);
    o.y = f2tf(v.y * rs * wv.y);
    o.z = f2tf(v.z * rs * wv.z);
    o.w = f2tf(v.w * rs * wv.w);
    ((float4*)(g_xn + (size_t)t * DIM))[threadIdx.x] = o;
}

// ---------------- RoPE tables --------------------------------------------------
__global__ void rope_table_kernel() {
    int idx = blockIdx.x * blockDim.x + threadIdx.x;
    if (idx >= Sln * 32) return;
    int si = idx >> 5, j = idx & 31;
    float inv = powf(10000.0f, -(float)j * (1.0f / 32.0f));
    float ang = (float)si * inv;
    g_cos[idx] = cosf(ang);
    g_sin[idx] = sinf(ang);
}

// ---------------- pass 2: fold 64 chunk partials -------------------------------
__global__ void kv_reduce2_kernel() {
    int bhk = blockIdx.x;
    int d = threadIdx.x;
    float akv = 0.f, ak = 0.f;
    #pragma unroll 8
    for (int c = 0; c < 64; c++) {
        akv += g_pkv[((c << 4) + bhk) * 64 + d];
        ak  += g_pks[((c << 4) + bhk) * 64 + d];
    }
    g_kv[bhk * 64 + d] = akv;
    g_ks[bhk * 64 + d] = ak;
}

// ---------------- per-token normalize -> Y (tf32-valued) into g_xn -------------
__global__ __launch_bounds__(256) void attn_out_kernel() {
    int t = blockIdx.x;
    int h = threadIdx.x >> 5;
    int lane = threadIdx.x & 31;
    int b = t >> 13;
    int hk = h >> 1;
    size_t qoff = (size_t)t * QKVN + h * HD;
    float q0 = g_qkv[qoff + lane];
    float q1 = g_qkv[qoff + 32 + lane];
    int koff = (b * 4 + hk) * 64;
    float z = q0 * g_ks[koff + lane] + q1 * g_ks[koff + 32 + lane];
    #pragma unroll
    for (int o = 16; o; o >>= 1) z += __shfl_xor_sync(0xffffffffu, z, o);
    float inv = 1.0f / (z + 1e-6f);
    size_t yoff = (size_t)t * DIM + h * HD;
    g_xn[yoff + lane]      = f2tf(q0 * g_kv[koff + lane]      * inv);
    g_xn[yoff + 32 + lane] = f2tf(q1 * g_kv[koff + 32 + lane] * inv);
}

// ---------------- host launcher -----------------------------------------------
extern "C" void kernel_launch(void* const* d_in, const int* in_sizes, int n_in,
                              void* d_out, int out_size) {
    (void)in_sizes; (void)n_in; (void)out_size;
    const float* x  = (const float*)d_in[0];
    const float* nw = (const float*)d_in[1];
    const float* wq = (const float*)d_in[2];
    const float* wk = (const float*)d_in[3];
    const float* wv = (const float*)d_in[4];
    const float* wo = (const float*)d_in[5];
    float* out = (float*)d_out;

    float *p_xn, *p_qkv, *p_w, *p_wo;
    cudaGetSymbolAddress((void**)&p_xn,  g_xn);
    cudaGetSymbolAddress((void**)&p_qkv, g_qkv);
    cudaGetSymbolAddress((void**)&p_w,   g_w);
    cudaGetSymbolAddress((void**)&p_wo,  g_wo);

    static cudaStream_t s_side = nullptr;
    static cudaEvent_t evFork = nullptr, evJoin = nullptr;
    if (!s_side) {
        cudaFuncSetAttribute(gemm_tf32mma, cudaFuncAttributeMaxDynamicSharedMemorySize,
                             G_SMEM_BYTES);
        cudaStreamCreateWithFlags(&s_side, cudaStreamNonBlocking);
        cudaEventCreateWithFlags(&evFork, cudaEventDisableTiming);
        cudaEventCreateWithFlags(&evJoin, cudaEventDisableTiming);
    }

    // fork: preamble (tables + weight rounding/packing) on side stream,
    // rmsnorm on main stream — independent, overlapped.
    cudaEventRecord(evFork, 0);
    cudaStreamWaitEvent(s_side, evFork, 0);
    rope_table_kernel<<<(Sln * 32 + 255) / 256, 256, 0, s_side>>>();
    round_tf32_kernel<<<(DIM * DIM / 4 + 255) / 256, 256, 0, s_side>>>(p_w, wq, DIM * DIM / 4);
    round_pack_kv<<<256, 128, 0, s_side>>>(wk, 0);
    round_pack_kv<<<256, 128, 0, s_side>>>(wv, 1);
    round_tf32_kernel<<<(DIM * DIM / 4 + 255) / 256, 256, 0, s_side>>>(p_wo, wo, DIM * DIM / 4);
    cudaEventRecord(evJoin, s_side);

    rmsnorm_kernel<<<NTOK, 128>>>(x, nw);
    cudaStreamWaitEvent(0, evJoin, 0);

    // fused QKV GEMM: Q rope+phi epilogue; KV tiles -> partial KV/Ksum (no store)
    gemm_tf32mma<<<dim3(QKVN / 128, NTOK / 128), 128, G_SMEM_BYTES>>>(p_xn, p_w, p_qkv, QKVN, 1);
    kv_reduce2_kernel<<<16, 64>>>();
    attn_out_kernel<<<NTOK, 256>>>();
    // output GEMM
    gemm_tf32mma<<<dim3(DIM / 128, NTOK / 128), 128, G_SMEM_BYTES>>>(p_xn, p_wo, out, DIM, 0);
}